// round 1
// baseline (speedup 1.0000x reference)
#include <cuda_runtime.h>
#include <math.h>

#define NN   100000
#define EE   3200000
#define IND  128
#define H1D  32
#define H2D  64
#define H3D  10
#define DPAD 12

// ---------------- scratch (device globals; no allocations allowed) ----------
__device__ float g_t[NN * H1D];     // x @ W_shared
__device__ float g_agg[NN * H1D];   // aggregation buffer (reused for both passes)
__device__ float g_h[NN * H1D];     // relu'd layer-1 output
__device__ float g_cnt[NN];         // edge-degree counts (float)
__device__ float g_dis[NN];         // deg^-1/2
__device__ __align__(16) float g_d2c[NN * DPAD];  // decoder-2 causal (10 used, 2 pad)
__device__ __align__(16) float g_d2n[NN * DPAD];  // decoder-2 non-causal
__device__ int g_is64;

// Edge index fetch: handles both int32 and int64 (values < 2^31 so the low
// word of a little-endian int64 is the value).
__device__ __forceinline__ int eidx(const int* __restrict__ w, int pos, int is64) {
    return is64 ? w[2 * pos] : w[pos];
}

// Detect int64 vs int32 edge_index: check hi-words of first 16 candidate i64s.
__global__ void k_detect(const int* __restrict__ w) {
    int all0 = 1;
    for (int i = 0; i < 16; i++)
        if (w[2 * i + 1] != 0) all0 = 0;
    g_is64 = all0;
}

__global__ void k_zero() {
    int i = blockIdx.x * blockDim.x + threadIdx.x;
    if (i < NN * H1D) g_agg[i] = 0.f;
    if (i < NN) g_cnt[i] = 0.f;
}

// t = x @ W_shared  (100000x128 @ 128x32). Warp per 4 rows, W in smem,
// x row held in registers, broadcast via shfl, lane = output column.
__global__ void k_gemm1(const float* __restrict__ x, const float* __restrict__ W) {
    __shared__ float Ws[IND * H1D];
    int tid = threadIdx.x;
    for (int i = tid; i < IND * H1D; i += 256) Ws[i] = W[i];
    __syncthreads();

    int gw = (blockIdx.x * 256 + tid) >> 5;
    int lane = tid & 31;
    int row0 = gw * 4;
    if (row0 >= NN) return;

    float xv[4][4];
#pragma unroll
    for (int rr = 0; rr < 4; rr++) {
        const float* xr = x + (size_t)(row0 + rr) * IND;
#pragma unroll
        for (int u = 0; u < 4; u++) xv[rr][u] = xr[u * 32 + lane];
    }
    float acc[4] = {0.f, 0.f, 0.f, 0.f};
#pragma unroll
    for (int u = 0; u < 4; u++) {
#pragma unroll 8
        for (int k2 = 0; k2 < 32; k2++) {
            float w = Ws[(u * 32 + k2) * H1D + lane];
#pragma unroll
            for (int rr = 0; rr < 4; rr++)
                acc[rr] += __shfl_sync(0xffffffffu, xv[rr][u], k2) * w;
        }
    }
#pragma unroll
    for (int rr = 0; rr < 4; rr++)
        g_t[(size_t)(row0 + rr) * H1D + lane] = acc[rr];
}

__global__ void k_deg(const int* __restrict__ ew) {
    int e = blockIdx.x * blockDim.x + threadIdx.x;
    if (e >= EE) return;
    int is64 = g_is64;
    int d = eidx(ew, EE + e, is64);
    atomicAdd(&g_cnt[d], 1.0f);
}

__global__ void k_dis() {
    int i = blockIdx.x * blockDim.x + threadIdx.x;
    if (i < NN) g_dis[i] = rsqrtf(g_cnt[i] + 1.0f);  // +1 self loop; deg>=1
}

// One warp handles 32 edges: coalesced index load, then per-edge 32-lane
// gather + scaled scatter-add of a 32-float row.
__global__ void k_agg(const int* __restrict__ ew, int which) {
    const float* __restrict__ src = which ? g_h : g_t;
    int lane = threadIdx.x & 31;
    long long wid = ((long long)blockIdx.x * blockDim.x + threadIdx.x) >> 5;
    long long base = wid * 32;
    if (base >= EE) return;
    int is64 = g_is64;
    int nume = (int)((EE - base) < 32 ? (EE - base) : 32);
    int e = (int)base + (lane < nume ? lane : 0);
    int s = eidx(ew, e, is64);
    int d = eidx(ew, EE + e, is64);
    float nrm0 = g_dis[s] * g_dis[d];
#pragma unroll 1
    for (int q = 0; q < nume; q++) {
        int ss = __shfl_sync(0xffffffffu, s, q);
        int dd = __shfl_sync(0xffffffffu, d, q);
        float nrm = __shfl_sync(0xffffffffu, nrm0, q);
        float v = src[(size_t)ss * H1D + lane] * nrm;
        atomicAdd(&g_agg[(size_t)dd * H1D + lane], v);
    }
}

// h = relu(agg + t*dis^2 + b); also re-zero g_agg for the second pass.
__global__ void k_relu(const float* __restrict__ b) {
    int idx = blockIdx.x * blockDim.x + threadIdx.x;
    if (idx >= NN * H1D) return;
    int i = idx >> 5;
    int c = idx & 31;
    float dd = g_dis[i];
    float v = g_agg[idx] + g_t[idx] * dd * dd + b[c];
    g_h[idx] = v > 0.f ? v : 0.f;
    g_agg[idx] = 0.f;
}

// Fused per-node tail: aggH -> (mu,lv)x2 -> z -> decoder d1 -> d2.
// Warp per 4 rows; lane = output column; a-row broadcast via shfl.
__global__ void k_mlp(
    const float* __restrict__ eps_c, const float* __restrict__ eps_n,
    const float* __restrict__ Wmc, const float* __restrict__ bmc,
    const float* __restrict__ Wmn, const float* __restrict__ bmn,
    const float* __restrict__ Wlc, const float* __restrict__ blc,
    const float* __restrict__ Wln, const float* __restrict__ bln,
    const float* __restrict__ Wd1c, const float* __restrict__ bd1c,
    const float* __restrict__ Wd2c, const float* __restrict__ bd2c,
    const float* __restrict__ Wd1n, const float* __restrict__ bd1n,
    const float* __restrict__ Wd2n, const float* __restrict__ bd2n,
    float* __restrict__ omc, float* __restrict__ omn,
    float* __restrict__ olc, float* __restrict__ oln) {
    // 0: mu_c, 1: lv_c, 2: mu_n, 3: lv_n  (each 32x64)
    __shared__ float sW[4][H1D * H2D];
    __shared__ float sD1[2][H2D * H1D];  // 0: causal, 1: non-causal (each 64x32)

    int tid = threadIdx.x;
    for (int i = tid; i < H1D * H2D; i += 256) {
        sW[0][i] = Wmc[i];
        sW[1][i] = Wlc[i];
        sW[2][i] = Wmn[i];
        sW[3][i] = Wln[i];
        sD1[0][i] = Wd1c[i];
        sD1[1][i] = Wd1n[i];
    }
    __syncthreads();

    int lane = tid & 31;
    int warp = tid >> 5;
    int row0 = (blockIdx.x * 8 + warp) * 4;
    if (row0 >= NN) return;

    float a[4];
#pragma unroll
    for (int rr = 0; rr < 4; rr++) {
        int i = row0 + rr;
        float dd = g_dis[i];
        a[rr] = g_agg[(size_t)i * H1D + lane] + g_h[(size_t)i * H1D + lane] * dd * dd;
    }

    float zc0[4], zc1[4], zn0[4], zn1[4];

    // ---- causal: mu_c and lv_c together ----
    {
        float bm0 = bmc[lane], bm1 = bmc[lane + 32];
        float bl0 = blc[lane], bl1 = blc[lane + 32];
        float m0[4], m1[4], l0[4], l1[4];
#pragma unroll
        for (int rr = 0; rr < 4; rr++) { m0[rr] = bm0; m1[rr] = bm1; l0[rr] = bl0; l1[rr] = bl1; }
#pragma unroll 4
        for (int k = 0; k < 32; k++) {
            float wm0 = sW[0][k * H2D + lane], wm1 = sW[0][k * H2D + lane + 32];
            float wl0 = sW[1][k * H2D + lane], wl1 = sW[1][k * H2D + lane + 32];
#pragma unroll
            for (int rr = 0; rr < 4; rr++) {
                float ak = __shfl_sync(0xffffffffu, a[rr], k);
                m0[rr] += ak * wm0; m1[rr] += ak * wm1;
                l0[rr] += ak * wl0; l1[rr] += ak * wl1;
            }
        }
#pragma unroll
        for (int rr = 0; rr < 4; rr++) {
            size_t i = row0 + rr;
            omc[i * H2D + lane] = m0[rr];
            omc[i * H2D + lane + 32] = m1[rr];
            olc[i * H2D + lane] = l0[rr];
            olc[i * H2D + lane + 32] = l1[rr];
            zc0[rr] = m0[rr] + eps_c[i * H2D + lane] * __expf(0.5f * l0[rr]);
            zc1[rr] = m1[rr] + eps_c[i * H2D + lane + 32] * __expf(0.5f * l1[rr]);
        }
    }
    // ---- non-causal: mu_n and lv_n together ----
    {
        float bm0 = bmn[lane], bm1 = bmn[lane + 32];
        float bl0 = bln[lane], bl1 = bln[lane + 32];
        float m0[4], m1[4], l0[4], l1[4];
#pragma unroll
        for (int rr = 0; rr < 4; rr++) { m0[rr] = bm0; m1[rr] = bm1; l0[rr] = bl0; l1[rr] = bl1; }
#pragma unroll 4
        for (int k = 0; k < 32; k++) {
            float wm0 = sW[2][k * H2D + lane], wm1 = sW[2][k * H2D + lane + 32];
            float wl0 = sW[3][k * H2D + lane], wl1 = sW[3][k * H2D + lane + 32];
#pragma unroll
            for (int rr = 0; rr < 4; rr++) {
                float ak = __shfl_sync(0xffffffffu, a[rr], k);
                m0[rr] += ak * wm0; m1[rr] += ak * wm1;
                l0[rr] += ak * wl0; l1[rr] += ak * wl1;
            }
        }
#pragma unroll
        for (int rr = 0; rr < 4; rr++) {
            size_t i = row0 + rr;
            omn[i * H2D + lane] = m0[rr];
            omn[i * H2D + lane + 32] = m1[rr];
            oln[i * H2D + lane] = l0[rr];
            oln[i * H2D + lane + 32] = l1[rr];
            zn0[rr] = m0[rr] + eps_n[i * H2D + lane] * __expf(0.5f * l0[rr]);
            zn1[rr] = m1[rr] + eps_n[i * H2D + lane + 32] * __expf(0.5f * l1[rr]);
        }
    }

    // ---- decoders (per row) ----
    int jj = lane < H3D ? lane : 0;
    float b1c = bd1c[lane], b1n = bd1n[lane];
    float b2c = bd2c[jj], b2n = bd2n[jj];
#pragma unroll
    for (int rr = 0; rr < 4; rr++) {
        size_t i = row0 + rr;
        // causal
        float d1 = b1c;
#pragma unroll 4
        for (int k = 0; k < 32; k++)
            d1 += __shfl_sync(0xffffffffu, zc0[rr], k) * sD1[0][k * H1D + lane];
#pragma unroll 4
        for (int k = 0; k < 32; k++)
            d1 += __shfl_sync(0xffffffffu, zc1[rr], k) * sD1[0][(32 + k) * H1D + lane];
        d1 = tanhf(d1);
        float acc = b2c;
#pragma unroll 4
        for (int k = 0; k < 32; k++)
            acc += __shfl_sync(0xffffffffu, d1, k) * Wd2c[k * H3D + jj];
        acc = tanhf(acc);
        if (lane < H3D) g_d2c[i * DPAD + lane] = acc;
        else if (lane < DPAD) g_d2c[i * DPAD + lane] = 0.f;
        // non-causal
        float e1 = b1n;
#pragma unroll 4
        for (int k = 0; k < 32; k++)
            e1 += __shfl_sync(0xffffffffu, zn0[rr], k) * sD1[1][k * H1D + lane];
#pragma unroll 4
        for (int k = 0; k < 32; k++)
            e1 += __shfl_sync(0xffffffffu, zn1[rr], k) * sD1[1][(32 + k) * H1D + lane];
        e1 = tanhf(e1);
        float acc2 = b2n;
#pragma unroll 4
        for (int k = 0; k < 32; k++)
            acc2 += __shfl_sync(0xffffffffu, e1, k) * Wd2n[k * H3D + jj];
        acc2 = tanhf(acc2);
        if (lane < H3D) g_d2n[i * DPAD + lane] = acc2;
        else if (lane < DPAD) g_d2n[i * DPAD + lane] = 0.f;
    }
}

// Per-edge inner products + sigmoid, both decoders in one pass.
__global__ void k_decode(const int* __restrict__ ew,
                         float* __restrict__ oc, float* __restrict__ on) {
    int e = blockIdx.x * blockDim.x + threadIdx.x;
    if (e >= EE) return;
    int is64 = g_is64;
    int s = eidx(ew, e, is64);
    int d = eidx(ew, EE + e, is64);

    const float4* pa = reinterpret_cast<const float4*>(g_d2c) + (size_t)s * 3;
    const float4* pb = reinterpret_cast<const float4*>(g_d2c) + (size_t)d * 3;
    float acc = 0.f;
#pragma unroll
    for (int q = 0; q < 3; q++) {
        float4 A = pa[q], B = pb[q];
        acc += A.x * B.x + A.y * B.y + A.z * B.z + A.w * B.w;
    }
    oc[e] = 1.f / (1.f + __expf(-acc));

    const float4* qa = reinterpret_cast<const float4*>(g_d2n) + (size_t)s * 3;
    const float4* qb = reinterpret_cast<const float4*>(g_d2n) + (size_t)d * 3;
    float acc2 = 0.f;
#pragma unroll
    for (int q = 0; q < 3; q++) {
        float4 A = qa[q], B = qb[q];
        acc2 += A.x * B.x + A.y * B.y + A.z * B.z + A.w * B.w;
    }
    on[e] = 1.f / (1.f + __expf(-acc2));
}

extern "C" void kernel_launch(void* const* d_in, const int* in_sizes, int n_in,
                              void* d_out, int out_size) {
    const float* x        = (const float*)d_in[0];
    const int*   ew       = (const int*)d_in[1];
    const float* eps_c    = (const float*)d_in[2];
    const float* eps_n    = (const float*)d_in[3];
    const float* W_shared = (const float*)d_in[4];
    const float* b_shared = (const float*)d_in[5];
    const float* Wmc = (const float*)d_in[6],  *bmc = (const float*)d_in[7];
    const float* Wmn = (const float*)d_in[8],  *bmn = (const float*)d_in[9];
    const float* Wlc = (const float*)d_in[10], *blc = (const float*)d_in[11];
    const float* Wln = (const float*)d_in[12], *bln = (const float*)d_in[13];
    const float* Wd1c = (const float*)d_in[14], *bd1c = (const float*)d_in[15];
    const float* Wd2c = (const float*)d_in[16], *bd2c = (const float*)d_in[17];
    const float* Wd1n = (const float*)d_in[18], *bd1n = (const float*)d_in[19];
    const float* Wd2n = (const float*)d_in[20], *bd2n = (const float*)d_in[21];

    float* out  = (float*)d_out;
    float* oewc = out;
    float* oewn = out + (size_t)EE;
    float* omc  = out + 2 * (size_t)EE;
    float* omn  = omc + (size_t)NN * H2D;
    float* olc  = omn + (size_t)NN * H2D;
    float* oln  = olc + (size_t)NN * H2D;

    k_detect<<<1, 1>>>(ew);
    k_zero<<<(NN * H1D + 255) / 256, 256>>>();
    k_gemm1<<<(NN / 4 + 7) / 8, 256>>>(x, W_shared);
    k_deg<<<(EE + 255) / 256, 256>>>(ew);
    k_dis<<<(NN + 255) / 256, 256>>>();
    k_agg<<<(EE / 32 + 7) / 8, 256>>>(ew, 0);  // aggregate t
    k_relu<<<(NN * H1D + 255) / 256, 256>>>(b_shared);
    k_agg<<<(EE / 32 + 7) / 8, 256>>>(ew, 1);  // aggregate h
    k_mlp<<<NN / 32, 256>>>(eps_c, eps_n, Wmc, bmc, Wmn, bmn, Wlc, blc, Wln, bln,
                            Wd1c, bd1c, Wd2c, bd2c, Wd1n, bd1n, Wd2n, bd2n,
                            omc, omn, olc, oln);
    k_decode<<<(EE + 255) / 256, 256>>>(ew, oewc, oewn);
}

// round 2
// speedup vs baseline: 1.0545x; 1.0545x over previous
#include <cuda_runtime.h>
#include <math.h>

#define NN   100000
#define EE   3200000
#define IND  128
#define H1D  32
#define H2D  64
#define H3D  10
#define NBLK 391          // ceil(NN/256)

// ---------------- scratch (device globals; no allocations allowed) ----------
__device__ float g_t[NN * H1D];       // x @ W_shared
__device__ float g_h[NN * H1D];       // relu'd layer-1 output
__device__ float g_agg[NN * H1D];     // second aggregation result
__device__ int   g_cnt[NN];           // per-dst edge counts (no self loop)
__device__ float g_dis[NN];           // (deg+1)^-1/2
__device__ int   g_ptr[NN];           // CSR row starts (exclusive)
__device__ int   g_cur[NN];           // fill cursors
__device__ int   g_bsum[512];         // scan block sums
__device__ int   g_esrc[EE];          // CSR: src node per slot
__device__ float g_enrm[EE];          // CSR: edge norm per slot
__device__ int2  g_e32[EE];           // packed (s,d) int32 per original edge
__device__ __align__(16) float g_d2[NN * 24];  // decoder-2 outputs: c[0:10), n[12:22)
__device__ int g_is64;

__device__ __forceinline__ int eidx(const int* __restrict__ w, long long pos, int is64) {
    return is64 ? w[2 * pos] : w[pos];
}

// Detect int64 vs int32 edge_index: hi-words of first 16 candidate i64s.
__global__ void k_detect(const int* __restrict__ w) {
    int all0 = 1;
    for (int i = 0; i < 16; i++)
        if (w[2 * i + 1] != 0) all0 = 0;
    g_is64 = all0;
}

__global__ void k_zcnt() {
    int i = blockIdx.x * blockDim.x + threadIdx.x;
    if (i < NN) g_cnt[i] = 0;
}

// Count degrees AND convert edge_index to packed int32 pairs (one int64 pass).
__global__ void k_deg(const int* __restrict__ ew) {
    int e = blockIdx.x * blockDim.x + threadIdx.x;
    if (e >= EE) return;
    int is64 = g_is64;
    int s = eidx(ew, e, is64);
    int d = eidx(ew, (long long)EE + e, is64);
    g_e32[e] = make_int2(s, d);
    atomicAdd(&g_cnt[d], 1);
}

__global__ void k_dis() {
    int i = blockIdx.x * blockDim.x + threadIdx.x;
    if (i < NN) g_dis[i] = rsqrtf((float)g_cnt[i] + 1.0f);
}

// ---- 3-phase exclusive prefix scan of g_cnt into g_ptr ----
__global__ void k_scan1() {
    __shared__ int s[256];
    int i = blockIdx.x * 256 + threadIdx.x;
    int v = (i < NN) ? g_cnt[i] : 0;
    s[threadIdx.x] = v;
    __syncthreads();
    for (int o = 1; o < 256; o <<= 1) {
        int t = (threadIdx.x >= o) ? s[threadIdx.x - o] : 0;
        __syncthreads();
        s[threadIdx.x] += t;
        __syncthreads();
    }
    if (i < NN) g_ptr[i] = s[threadIdx.x];           // inclusive within block
    if (threadIdx.x == 255) g_bsum[blockIdx.x] = s[255];
}

__global__ void k_scan2() {
    __shared__ int s[512];
    int tid = threadIdx.x;
    int v = (tid < NBLK) ? g_bsum[tid] : 0;
    s[tid] = v;
    __syncthreads();
    for (int o = 1; o < 512; o <<= 1) {
        int t = (tid >= o) ? s[tid - o] : 0;
        __syncthreads();
        s[tid] += t;
        __syncthreads();
    }
    g_bsum[tid] = s[tid] - v;                        // exclusive block offsets
}

__global__ void k_scan3() {
    int i = blockIdx.x * 256 + threadIdx.x;
    if (i >= NN) return;
    int start = g_ptr[i] + g_bsum[i >> 8] - g_cnt[i];
    g_ptr[i] = start;
    g_cur[i] = start;
}

// Scatter edges into CSR slots with precomputed norm.
__global__ void k_fill() {
    int e = blockIdx.x * blockDim.x + threadIdx.x;
    if (e >= EE) return;
    int2 sd = g_e32[e];
    float nrm = g_dis[sd.x] * g_dis[sd.y];
    int pos = atomicAdd(&g_cur[sd.y], 1);
    g_esrc[pos] = sd.x;
    g_enrm[pos] = nrm;
}

// t = x @ W_shared  (100000x128 @ 128x32). Warp per 4 rows, W in smem.
__global__ void k_gemm1(const float* __restrict__ x, const float* __restrict__ W) {
    __shared__ float Ws[IND * H1D];
    int tid = threadIdx.x;
    for (int i = tid; i < IND * H1D; i += 256) Ws[i] = W[i];
    __syncthreads();

    int gw = (blockIdx.x * 256 + tid) >> 5;
    int lane = tid & 31;
    int row0 = gw * 4;
    if (row0 >= NN) return;

    float xv[4][4];
#pragma unroll
    for (int rr = 0; rr < 4; rr++) {
        const float* xr = x + (size_t)(row0 + rr) * IND;
#pragma unroll
        for (int u = 0; u < 4; u++) xv[rr][u] = xr[u * 32 + lane];
    }
    float acc[4] = {0.f, 0.f, 0.f, 0.f};
#pragma unroll
    for (int u = 0; u < 4; u++) {
#pragma unroll 8
        for (int k2 = 0; k2 < 32; k2++) {
            float w = Ws[(u * 32 + k2) * H1D + lane];
#pragma unroll
            for (int rr = 0; rr < 4; rr++)
                acc[rr] += __shfl_sync(0xffffffffu, xv[rr][u], k2) * w;
        }
    }
#pragma unroll
    for (int rr = 0; rr < 4; rr++)
        g_t[(size_t)(row0 + rr) * H1D + lane] = acc[rr];
}

// CSR gather aggregation: warp per dst node. mode 0: t -> h (bias+relu).
// mode 1: h -> agg (plain). Self-loop (dis^2) folded in. No atomics.
__global__ void k_aggcsr(const float* __restrict__ b, int mode) {
    const float* __restrict__ src = mode ? g_h : g_t;
    int lane = threadIdx.x & 31;
    int node = (blockIdx.x * blockDim.x + threadIdx.x) >> 5;
    if (node >= NN) return;

    int start = g_ptr[node];
    int n = g_cnt[node];
    float dd = g_dis[node];
    float acc = src[(size_t)node * H1D + lane] * dd * dd;

    int j = start;
    int rem = n;
    while (rem >= 32) {
        int   sj = g_esrc[j + lane];
        float nj = g_enrm[j + lane];
#pragma unroll
        for (int q = 0; q < 32; q++) {
            int ss = __shfl_sync(0xffffffffu, sj, q);
            float nn = __shfl_sync(0xffffffffu, nj, q);
            acc += src[(size_t)ss * H1D + lane] * nn;
        }
        j += 32;
        rem -= 32;
    }
    if (rem > 0) {
        int   sj = (lane < rem) ? g_esrc[j + lane] : 0;
        float nj = (lane < rem) ? g_enrm[j + lane] : 0.f;
        for (int q = 0; q < rem; q++) {
            int ss = __shfl_sync(0xffffffffu, sj, q);
            float nn = __shfl_sync(0xffffffffu, nj, q);
            acc += src[(size_t)ss * H1D + lane] * nn;
        }
    }

    if (mode == 0) {
        float v = acc + b[lane];
        g_h[(size_t)node * H1D + lane] = v > 0.f ? v : 0.f;
    } else {
        g_agg[(size_t)node * H1D + lane] = acc;
    }
}

// Fused per-node tail: agg -> (mu,lv)x2 -> z -> decoder d1 -> d2.
__global__ void k_mlp(
    const float* __restrict__ eps_c, const float* __restrict__ eps_n,
    const float* __restrict__ Wmc, const float* __restrict__ bmc,
    const float* __restrict__ Wmn, const float* __restrict__ bmn,
    const float* __restrict__ Wlc, const float* __restrict__ blc,
    const float* __restrict__ Wln, const float* __restrict__ bln,
    const float* __restrict__ Wd1c, const float* __restrict__ bd1c,
    const float* __restrict__ Wd2c, const float* __restrict__ bd2c,
    const float* __restrict__ Wd1n, const float* __restrict__ bd1n,
    const float* __restrict__ Wd2n, const float* __restrict__ bd2n,
    float* __restrict__ omc, float* __restrict__ omn,
    float* __restrict__ olc, float* __restrict__ oln) {
    __shared__ float sW[4][H1D * H2D];   // mu_c, lv_c, mu_n, lv_n
    __shared__ float sD1[2][H2D * H1D];  // causal / non-causal

    int tid = threadIdx.x;
    for (int i = tid; i < H1D * H2D; i += 256) {
        sW[0][i] = Wmc[i];
        sW[1][i] = Wlc[i];
        sW[2][i] = Wmn[i];
        sW[3][i] = Wln[i];
        sD1[0][i] = Wd1c[i];
        sD1[1][i] = Wd1n[i];
    }
    __syncthreads();

    int lane = tid & 31;
    int warp = tid >> 5;
    int row0 = (blockIdx.x * 8 + warp) * 4;
    if (row0 >= NN) return;

    float a[4];
#pragma unroll
    for (int rr = 0; rr < 4; rr++)
        a[rr] = g_agg[(size_t)(row0 + rr) * H1D + lane];

    float zc0[4], zc1[4], zn0[4], zn1[4];

    {
        float bm0 = bmc[lane], bm1 = bmc[lane + 32];
        float bl0 = blc[lane], bl1 = blc[lane + 32];
        float m0[4], m1[4], l0[4], l1[4];
#pragma unroll
        for (int rr = 0; rr < 4; rr++) { m0[rr] = bm0; m1[rr] = bm1; l0[rr] = bl0; l1[rr] = bl1; }
#pragma unroll 4
        for (int k = 0; k < 32; k++) {
            float wm0 = sW[0][k * H2D + lane], wm1 = sW[0][k * H2D + lane + 32];
            float wl0 = sW[1][k * H2D + lane], wl1 = sW[1][k * H2D + lane + 32];
#pragma unroll
            for (int rr = 0; rr < 4; rr++) {
                float ak = __shfl_sync(0xffffffffu, a[rr], k);
                m0[rr] += ak * wm0; m1[rr] += ak * wm1;
                l0[rr] += ak * wl0; l1[rr] += ak * wl1;
            }
        }
#pragma unroll
        for (int rr = 0; rr < 4; rr++) {
            size_t i = row0 + rr;
            omc[i * H2D + lane] = m0[rr];
            omc[i * H2D + lane + 32] = m1[rr];
            olc[i * H2D + lane] = l0[rr];
            olc[i * H2D + lane + 32] = l1[rr];
            zc0[rr] = m0[rr] + eps_c[i * H2D + lane] * __expf(0.5f * l0[rr]);
            zc1[rr] = m1[rr] + eps_c[i * H2D + lane + 32] * __expf(0.5f * l1[rr]);
        }
    }
    {
        float bm0 = bmn[lane], bm1 = bmn[lane + 32];
        float bl0 = bln[lane], bl1 = bln[lane + 32];
        float m0[4], m1[4], l0[4], l1[4];
#pragma unroll
        for (int rr = 0; rr < 4; rr++) { m0[rr] = bm0; m1[rr] = bm1; l0[rr] = bl0; l1[rr] = bl1; }
#pragma unroll 4
        for (int k = 0; k < 32; k++) {
            float wm0 = sW[2][k * H2D + lane], wm1 = sW[2][k * H2D + lane + 32];
            float wl0 = sW[3][k * H2D + lane], wl1 = sW[3][k * H2D + lane + 32];
#pragma unroll
            for (int rr = 0; rr < 4; rr++) {
                float ak = __shfl_sync(0xffffffffu, a[rr], k);
                m0[rr] += ak * wm0; m1[rr] += ak * wm1;
                l0[rr] += ak * wl0; l1[rr] += ak * wl1;
            }
        }
#pragma unroll
        for (int rr = 0; rr < 4; rr++) {
            size_t i = row0 + rr;
            omn[i * H2D + lane] = m0[rr];
            omn[i * H2D + lane + 32] = m1[rr];
            oln[i * H2D + lane] = l0[rr];
            oln[i * H2D + lane + 32] = l1[rr];
            zn0[rr] = m0[rr] + eps_n[i * H2D + lane] * __expf(0.5f * l0[rr]);
            zn1[rr] = m1[rr] + eps_n[i * H2D + lane + 32] * __expf(0.5f * l1[rr]);
        }
    }

    int jj = lane < H3D ? lane : 0;
    float b1c = bd1c[lane], b1n = bd1n[lane];
    float b2c = bd2c[jj], b2n = bd2n[jj];
#pragma unroll
    for (int rr = 0; rr < 4; rr++) {
        size_t i = row0 + rr;
        float d1 = b1c;
#pragma unroll 4
        for (int k = 0; k < 32; k++)
            d1 += __shfl_sync(0xffffffffu, zc0[rr], k) * sD1[0][k * H1D + lane];
#pragma unroll 4
        for (int k = 0; k < 32; k++)
            d1 += __shfl_sync(0xffffffffu, zc1[rr], k) * sD1[0][(32 + k) * H1D + lane];
        d1 = tanhf(d1);
        float acc = b2c;
#pragma unroll 4
        for (int k = 0; k < 32; k++)
            acc += __shfl_sync(0xffffffffu, d1, k) * Wd2c[k * H3D + jj];
        acc = tanhf(acc);

        float e1 = b1n;
#pragma unroll 4
        for (int k = 0; k < 32; k++)
            e1 += __shfl_sync(0xffffffffu, zn0[rr], k) * sD1[1][k * H1D + lane];
#pragma unroll 4
        for (int k = 0; k < 32; k++)
            e1 += __shfl_sync(0xffffffffu, zn1[rr], k) * sD1[1][(32 + k) * H1D + lane];
        e1 = tanhf(e1);
        float acc2 = b2n;
#pragma unroll 4
        for (int k = 0; k < 32; k++)
            acc2 += __shfl_sync(0xffffffffu, e1, k) * Wd2n[k * H3D + jj];
        acc2 = tanhf(acc2);

        if (lane < 12) {
            g_d2[i * 24 + lane]      = (lane < H3D) ? acc  : 0.f;
            g_d2[i * 24 + 12 + lane] = (lane < H3D) ? acc2 : 0.f;
        }
    }
}

// Per-edge inner products + sigmoid, both decoders in one pass.
__global__ void k_decode(float* __restrict__ oc, float* __restrict__ on) {
    int e = blockIdx.x * blockDim.x + threadIdx.x;
    if (e >= EE) return;
    int2 sd = g_e32[e];

    const float4* pa = reinterpret_cast<const float4*>(g_d2 + (size_t)sd.x * 24);
    const float4* pb = reinterpret_cast<const float4*>(g_d2 + (size_t)sd.y * 24);
    float accc = 0.f, accn = 0.f;
#pragma unroll
    for (int q = 0; q < 3; q++) {
        float4 A = pa[q], B = pb[q];
        accc += A.x * B.x + A.y * B.y + A.z * B.z + A.w * B.w;
    }
#pragma unroll
    for (int q = 3; q < 6; q++) {
        float4 A = pa[q], B = pb[q];
        accn += A.x * B.x + A.y * B.y + A.z * B.z + A.w * B.w;
    }
    oc[e] = 1.f / (1.f + __expf(-accc));
    on[e] = 1.f / (1.f + __expf(-accn));
}

extern "C" void kernel_launch(void* const* d_in, const int* in_sizes, int n_in,
                              void* d_out, int out_size) {
    const float* x        = (const float*)d_in[0];
    const int*   ew       = (const int*)d_in[1];
    const float* eps_c    = (const float*)d_in[2];
    const float* eps_n    = (const float*)d_in[3];
    const float* W_shared = (const float*)d_in[4];
    const float* b_shared = (const float*)d_in[5];
    const float* Wmc = (const float*)d_in[6],  *bmc = (const float*)d_in[7];
    const float* Wmn = (const float*)d_in[8],  *bmn = (const float*)d_in[9];
    const float* Wlc = (const float*)d_in[10], *blc = (const float*)d_in[11];
    const float* Wln = (const float*)d_in[12], *bln = (const float*)d_in[13];
    const float* Wd1c = (const float*)d_in[14], *bd1c = (const float*)d_in[15];
    const float* Wd2c = (const float*)d_in[16], *bd2c = (const float*)d_in[17];
    const float* Wd1n = (const float*)d_in[18], *bd1n = (const float*)d_in[19];
    const float* Wd2n = (const float*)d_in[20], *bd2n = (const float*)d_in[21];

    float* out  = (float*)d_out;
    float* oewc = out;
    float* oewn = out + (size_t)EE;
    float* omc  = out + 2 * (size_t)EE;
    float* omn  = omc + (size_t)NN * H2D;
    float* olc  = omn + (size_t)NN * H2D;
    float* oln  = olc + (size_t)NN * H2D;

    k_detect<<<1, 1>>>(ew);
    k_zcnt<<<(NN + 255) / 256, 256>>>();
    k_deg<<<(EE + 255) / 256, 256>>>(ew);
    k_dis<<<(NN + 255) / 256, 256>>>();
    k_scan1<<<NBLK, 256>>>();
    k_scan2<<<1, 512>>>();
    k_scan3<<<NBLK, 256>>>();
    k_fill<<<(EE + 255) / 256, 256>>>();
    k_gemm1<<<(NN / 4 + 7) / 8, 256>>>(x, W_shared);
    k_aggcsr<<<(NN + 7) / 8, 256>>>(b_shared, 0);   // t -> h (bias+relu)
    k_aggcsr<<<(NN + 7) / 8, 256>>>(nullptr, 1);    // h -> agg
    k_mlp<<<NN / 32, 256>>>(eps_c, eps_n, Wmc, bmc, Wmn, bmn, Wlc, blc, Wln, bln,
                            Wd1c, bd1c, Wd2c, bd2c, Wd1n, bd1n, Wd2n, bd2n,
                            omc, omn, olc, oln);
    k_decode<<<(EE + 255) / 256, 256>>>(oewc, oewn);
}

// round 3
// speedup vs baseline: 1.1791x; 1.1182x over previous
#include <cuda_runtime.h>
#include <math.h>

#define NN   100000
#define EE   3200000
#define IND  128
#define H1D  32
#define H2D  64
#define H3D  10
#define NBLK 391          // ceil(NN/256)

typedef unsigned long long ull;

// ---------------- scratch (device globals; no allocations allowed) ----------
__device__ float g_t[NN * H1D];       // x @ W_shared
__device__ float g_h[NN * H1D];       // relu'd layer-1 output
__device__ float g_agg[NN * H1D];     // second aggregation result
__device__ int   g_cnt[NN];           // per-dst edge counts (no self loop)
__device__ float g_dis[NN];           // (deg+1)^-1/2
__device__ int   g_ptr[NN];           // CSR row starts (exclusive)
__device__ int   g_cur[NN];           // fill cursors
__device__ int   g_bsum[512];         // scan block sums
__device__ int2  g_epk[EE];           // CSR slot: {src, bits(norm)}
__device__ int2  g_e32[EE];           // packed (s,d) int32 per original edge
__device__ __align__(16) float g_d2[NN * 20];  // decoder-2: c[0:10) | n[10:20)
__device__ int g_is64;

// ---------------- f32x2 helpers (sm_103a packed fp32) ----------------------
__device__ __forceinline__ ull pack2(float lo, float hi) {
    ull r; asm("mov.b64 %0,{%1,%2};" : "=l"(r) : "f"(lo), "f"(hi)); return r;
}
__device__ __forceinline__ ull splat2(float v) { return pack2(v, v); }
__device__ __forceinline__ ull fma2(ull a, ull b, ull c) {
    ull d; asm("fma.rn.f32x2 %0,%1,%2,%3;" : "=l"(d) : "l"(a), "l"(b), "l"(c)); return d;
}
__device__ __forceinline__ void unpack2(ull v, float& lo, float& hi) {
    asm("mov.b64 {%0,%1},%2;" : "=f"(lo), "=f"(hi) : "l"(v));
}
__device__ __forceinline__ float ftanh(float x) {
    float e = __expf(2.0f * x);               // inf-safe: x>>0 -> 1, x<<0 -> -1
    return 1.0f - __fdividef(2.0f, e + 1.0f);
}

__device__ __forceinline__ int eidx(const int* __restrict__ w, long long pos, int is64) {
    return is64 ? w[2 * pos] : w[pos];
}

// Detect int64 vs int32 edge_index + zero counts (fused).
__global__ void k_boot(const int* __restrict__ w) {
    int i = blockIdx.x * 256 + threadIdx.x;
    if (i < NN) g_cnt[i] = 0;
    if (i == 0) {
        int all0 = 1;
        for (int q = 0; q < 16; q++)
            if (w[2 * q + 1] != 0) all0 = 0;
        g_is64 = all0;
    }
}

// Count degrees AND convert edge_index to packed int32 pairs (one int64 pass).
__global__ void k_deg(const int* __restrict__ ew) {
    int e = blockIdx.x * blockDim.x + threadIdx.x;
    if (e >= EE) return;
    int is64 = g_is64;
    int s = eidx(ew, e, is64);
    int d = eidx(ew, (long long)EE + e, is64);
    g_e32[e] = make_int2(s, d);
    atomicAdd(&g_cnt[d], 1);
}

// ---- 3-phase exclusive prefix scan of g_cnt into g_ptr (+ dis fused) ----
__global__ void k_scan1() {
    __shared__ int s[256];
    int i = blockIdx.x * 256 + threadIdx.x;
    int v = (i < NN) ? g_cnt[i] : 0;
    if (i < NN) g_dis[i] = rsqrtf((float)v + 1.0f);
    s[threadIdx.x] = v;
    __syncthreads();
    for (int o = 1; o < 256; o <<= 1) {
        int t = (threadIdx.x >= o) ? s[threadIdx.x - o] : 0;
        __syncthreads();
        s[threadIdx.x] += t;
        __syncthreads();
    }
    if (i < NN) g_ptr[i] = s[threadIdx.x];           // inclusive within block
    if (threadIdx.x == 255) g_bsum[blockIdx.x] = s[255];
}

__global__ void k_scan2() {
    __shared__ int s[512];
    int tid = threadIdx.x;
    int v = (tid < NBLK) ? g_bsum[tid] : 0;
    s[tid] = v;
    __syncthreads();
    for (int o = 1; o < 512; o <<= 1) {
        int t = (tid >= o) ? s[tid - o] : 0;
        __syncthreads();
        s[tid] += t;
        __syncthreads();
    }
    g_bsum[tid] = s[tid] - v;                        // exclusive block offsets
}

__global__ void k_scan3() {
    int i = blockIdx.x * 256 + threadIdx.x;
    if (i >= NN) return;
    int start = g_ptr[i] + g_bsum[i >> 8] - g_cnt[i];
    g_ptr[i] = start;
    g_cur[i] = start;
}

// Scatter edges into CSR slots: one packed 8B record {src, norm}.
__global__ void k_fill() {
    int e = blockIdx.x * blockDim.x + threadIdx.x;
    if (e >= EE) return;
    int2 sd = g_e32[e];
    float nrm = g_dis[sd.x] * g_dis[sd.y];
    int pos = atomicAdd(&g_cur[sd.y], 1);
    g_epk[pos] = make_int2(sd.x, __float_as_int(nrm));
}

// t = x @ W_shared  (100000x128 @ 128x32). Warp per 4 rows, W in smem.
__global__ void k_gemm1(const float* __restrict__ x, const float* __restrict__ W) {
    __shared__ float Ws[IND * H1D];
    int tid = threadIdx.x;
    for (int i = tid; i < IND * H1D; i += 256) Ws[i] = W[i];
    __syncthreads();

    int gw = (blockIdx.x * 256 + tid) >> 5;
    int lane = tid & 31;
    int row0 = gw * 4;
    if (row0 >= NN) return;

    float xv[4][4];
#pragma unroll
    for (int rr = 0; rr < 4; rr++) {
        const float* xr = x + (size_t)(row0 + rr) * IND;
#pragma unroll
        for (int u = 0; u < 4; u++) xv[rr][u] = xr[u * 32 + lane];
    }
    float acc[4] = {0.f, 0.f, 0.f, 0.f};
#pragma unroll
    for (int u = 0; u < 4; u++) {
#pragma unroll 8
        for (int k2 = 0; k2 < 32; k2++) {
            float w = Ws[(u * 32 + k2) * H1D + lane];
#pragma unroll
            for (int rr = 0; rr < 4; rr++)
                acc[rr] += __shfl_sync(0xffffffffu, xv[rr][u], k2) * w;
        }
    }
#pragma unroll
    for (int rr = 0; rr < 4; rr++)
        g_t[(size_t)(row0 + rr) * H1D + lane] = acc[rr];
}

// CSR gather aggregation: warp per dst node, smem-staged edge records.
// mode 0: t -> h (bias+relu). mode 1: h -> agg. Self-loop folded in. No atomics.
__global__ void k_aggcsr(const float* __restrict__ b, int mode) {
    __shared__ int2 sE[8][32];
    const float* __restrict__ src = mode ? g_h : g_t;
    int lane = threadIdx.x & 31;
    int w = threadIdx.x >> 5;
    int node = (blockIdx.x * blockDim.x + threadIdx.x) >> 5;
    if (node >= NN) return;

    int j = g_ptr[node];
    int rem = g_cnt[node];
    float dd = g_dis[node];
    float acc = src[(size_t)node * H1D + lane] * dd * dd;

    while (rem >= 32) {
        sE[w][lane] = g_epk[j + lane];
        __syncwarp();
#pragma unroll
        for (int q = 0; q < 32; q++) {
            int2 e = sE[w][q];
            acc += src[(size_t)e.x * H1D + lane] * __int_as_float(e.y);
        }
        __syncwarp();
        j += 32;
        rem -= 32;
    }
    if (rem > 0) {
        if (lane < rem) sE[w][lane] = g_epk[j + lane];
        __syncwarp();
        for (int q = 0; q < rem; q++) {
            int2 e = sE[w][q];
            acc += src[(size_t)e.x * H1D + lane] * __int_as_float(e.y);
        }
    }

    if (mode == 0) {
        float v = acc + b[lane];
        g_h[(size_t)node * H1D + lane] = v > 0.f ? v : 0.f;
    } else {
        g_agg[(size_t)node * H1D + lane] = acc;
    }
}

// Fused per-node tail: agg -> (mu,lv)x2 -> z -> decoder d1 -> d2.
// f32x2 packed math with pre-packed weight pairs in smem.
__global__ void k_mlp(
    const float* __restrict__ eps_c, const float* __restrict__ eps_n,
    const float* __restrict__ Wmc, const float* __restrict__ bmc,
    const float* __restrict__ Wmn, const float* __restrict__ bmn,
    const float* __restrict__ Wlc, const float* __restrict__ blc,
    const float* __restrict__ Wln, const float* __restrict__ bln,
    const float* __restrict__ Wd1c, const float* __restrict__ bd1c,
    const float* __restrict__ Wd2c, const float* __restrict__ bd2c,
    const float* __restrict__ Wd1n, const float* __restrict__ bd1n,
    const float* __restrict__ Wd2n, const float* __restrict__ bd2n,
    float* __restrict__ omc, float* __restrict__ omn,
    float* __restrict__ olc, float* __restrict__ oln) {
    // packed weight pairs: sWp[m][k*32+lane] = {W[k*64+lane], W[k*64+lane+32]}
    __shared__ ull sWp[4][H1D * 32];    // mu_c, lv_c, mu_n, lv_n (8KB each)
    // sD1p[d][k*32+lane] = {Wd1[k*32+lane], Wd1[(k+32)*32+lane]}
    __shared__ ull sD1p[2][32 * 32];    // 8KB each
    // sD2p[d][kp*10+j] = {Wd2[2kp*10+j], Wd2[(2kp+1)*10+j]}
    __shared__ ull sD2p[2][16 * H3D];

    int tid = threadIdx.x;
    for (int i = tid; i < 1024; i += 256) {
        int k = i >> 5, lane = i & 31;
        sWp[0][i] = pack2(Wmc[k * 64 + lane], Wmc[k * 64 + lane + 32]);
        sWp[1][i] = pack2(Wlc[k * 64 + lane], Wlc[k * 64 + lane + 32]);
        sWp[2][i] = pack2(Wmn[k * 64 + lane], Wmn[k * 64 + lane + 32]);
        sWp[3][i] = pack2(Wln[k * 64 + lane], Wln[k * 64 + lane + 32]);
        sD1p[0][i] = pack2(Wd1c[k * 32 + lane], Wd1c[(k + 32) * 32 + lane]);
        sD1p[1][i] = pack2(Wd1n[k * 32 + lane], Wd1n[(k + 32) * 32 + lane]);
    }
    for (int i = tid; i < 16 * H3D; i += 256) {
        int kp = i / H3D, j = i % H3D;
        sD2p[0][i] = pack2(Wd2c[(2 * kp) * H3D + j], Wd2c[(2 * kp + 1) * H3D + j]);
        sD2p[1][i] = pack2(Wd2n[(2 * kp) * H3D + j], Wd2n[(2 * kp + 1) * H3D + j]);
    }
    __syncthreads();

    int lane = tid & 31;
    int warp = tid >> 5;
    int row0 = (blockIdx.x * 8 + warp) * 4;
    if (row0 >= NN) return;

    float a[4];
#pragma unroll
    for (int rr = 0; rr < 4; rr++)
        a[rr] = g_agg[(size_t)(row0 + rr) * H1D + lane];

    int jj = lane < H3D ? lane : 0;

#pragma unroll
    for (int half = 0; half < 2; half++) {   // 0: causal, 1: non-causal
        const ull* Wm = sWp[half * 2];
        const ull* Wl = sWp[half * 2 + 1];
        const ull* D1 = sD1p[half];
        const ull* D2 = sD2p[half];
        const float* bm = half ? bmn : bmc;
        const float* bl = half ? bln : blc;
        const float* b1 = half ? bd1n : bd1c;
        const float* b2 = half ? bd2n : bd2c;
        const float* eps = half ? eps_n : eps_c;
        float* om = half ? omn : omc;
        float* ol = half ? oln : olc;

        ull m01[4], l01[4];
        {
            ull bmp = pack2(bm[lane], bm[lane + 32]);
            ull blp = pack2(bl[lane], bl[lane + 32]);
#pragma unroll
            for (int rr = 0; rr < 4; rr++) { m01[rr] = bmp; l01[rr] = blp; }
        }
#pragma unroll 8
        for (int k = 0; k < 32; k++) {
            ull wm = Wm[k * 32 + lane];
            ull wl = Wl[k * 32 + lane];
#pragma unroll
            for (int rr = 0; rr < 4; rr++) {
                ull a2 = splat2(__shfl_sync(0xffffffffu, a[rr], k));
                m01[rr] = fma2(a2, wm, m01[rr]);
                l01[rr] = fma2(a2, wl, l01[rr]);
            }
        }

        float z0[4], z1[4];
#pragma unroll
        for (int rr = 0; rr < 4; rr++) {
            size_t i = row0 + rr;
            float m0, m1, l0, l1;
            unpack2(m01[rr], m0, m1);
            unpack2(l01[rr], l0, l1);
            om[i * H2D + lane] = m0;
            om[i * H2D + lane + 32] = m1;
            ol[i * H2D + lane] = l0;
            ol[i * H2D + lane + 32] = l1;
            z0[rr] = m0 + eps[i * H2D + lane] * __expf(0.5f * l0);
            z1[rr] = m1 + eps[i * H2D + lane + 32] * __expf(0.5f * l1);
        }

        float b1v = b1[lane];
        float b2v = b2[jj];
#pragma unroll
        for (int rr = 0; rr < 4; rr++) {
            size_t i = row0 + rr;
            // d1 = tanh(z @ Wd1 + b1): 64 k-terms as 32 packed pairs (k, k+32)
            ull acc1 = pack2(b1v, 0.f);
#pragma unroll 8
            for (int k = 0; k < 32; k++) {
                ull zp = pack2(__shfl_sync(0xffffffffu, z0[rr], k),
                               __shfl_sync(0xffffffffu, z1[rr], k));
                acc1 = fma2(zp, D1[k * 32 + lane], acc1);
            }
            float s0, s1;
            unpack2(acc1, s0, s1);
            float d1 = ftanh(s0 + s1);
            // d2 = tanh(d1 @ Wd2 + b2): 32 k-terms as 16 packed pairs
            ull acc2 = pack2(b2v, 0.f);
#pragma unroll 8
            for (int kp = 0; kp < 16; kp++) {
                ull dp = pack2(__shfl_sync(0xffffffffu, d1, 2 * kp),
                               __shfl_sync(0xffffffffu, d1, 2 * kp + 1));
                acc2 = fma2(dp, D2[kp * H3D + jj], acc2);
            }
            unpack2(acc2, s0, s1);
            float v = ftanh(s0 + s1);
            if (lane < H3D) g_d2[i * 20 + half * H3D + lane] = v;
        }
    }
}

// Per-edge inner products + sigmoid, both decoders in one pass. 80B records.
__global__ void k_decode(float* __restrict__ oc, float* __restrict__ on) {
    int e = blockIdx.x * blockDim.x + threadIdx.x;
    if (e >= EE) return;
    int2 sd = g_e32[e];

    const float4* pa = reinterpret_cast<const float4*>(g_d2 + (size_t)sd.x * 20);
    const float4* pb = reinterpret_cast<const float4*>(g_d2 + (size_t)sd.y * 20);
    float4 a0 = pa[0], a1 = pa[1], a2 = pa[2], a3 = pa[3], a4 = pa[4];
    float4 b0 = pb[0], b1 = pb[1], b2 = pb[2], b3 = pb[3], b4 = pb[4];

    float accc = a0.x * b0.x + a0.y * b0.y + a0.z * b0.z + a0.w * b0.w
               + a1.x * b1.x + a1.y * b1.y + a1.z * b1.z + a1.w * b1.w
               + a2.x * b2.x + a2.y * b2.y;
    float accn = a2.z * b2.z + a2.w * b2.w
               + a3.x * b3.x + a3.y * b3.y + a3.z * b3.z + a3.w * b3.w
               + a4.x * b4.x + a4.y * b4.y + a4.z * b4.z + a4.w * b4.w;
    oc[e] = __fdividef(1.f, 1.f + __expf(-accc));
    on[e] = __fdividef(1.f, 1.f + __expf(-accn));
}

extern "C" void kernel_launch(void* const* d_in, const int* in_sizes, int n_in,
                              void* d_out, int out_size) {
    const float* x        = (const float*)d_in[0];
    const int*   ew       = (const int*)d_in[1];
    const float* eps_c    = (const float*)d_in[2];
    const float* eps_n    = (const float*)d_in[3];
    const float* W_shared = (const float*)d_in[4];
    const float* b_shared = (const float*)d_in[5];
    const float* Wmc = (const float*)d_in[6],  *bmc = (const float*)d_in[7];
    const float* Wmn = (const float*)d_in[8],  *bmn = (const float*)d_in[9];
    const float* Wlc = (const float*)d_in[10], *blc = (const float*)d_in[11];
    const float* Wln = (const float*)d_in[12], *bln = (const float*)d_in[13];
    const float* Wd1c = (const float*)d_in[14], *bd1c = (const float*)d_in[15];
    const float* Wd2c = (const float*)d_in[16], *bd2c = (const float*)d_in[17];
    const float* Wd1n = (const float*)d_in[18], *bd1n = (const float*)d_in[19];
    const float* Wd2n = (const float*)d_in[20], *bd2n = (const float*)d_in[21];

    float* out  = (float*)d_out;
    float* oewc = out;
    float* oewn = out + (size_t)EE;
    float* omc  = out + 2 * (size_t)EE;
    float* omn  = omc + (size_t)NN * H2D;
    float* olc  = omn + (size_t)NN * H2D;
    float* oln  = olc + (size_t)NN * H2D;

    k_boot<<<NBLK, 256>>>(ew);
    k_deg<<<(EE + 255) / 256, 256>>>(ew);
    k_scan1<<<NBLK, 256>>>();
    k_scan2<<<1, 512>>>();
    k_scan3<<<NBLK, 256>>>();
    k_fill<<<(EE + 255) / 256, 256>>>();
    k_gemm1<<<(NN / 4 + 7) / 8, 256>>>(x, W_shared);
    k_aggcsr<<<(NN + 7) / 8, 256>>>(b_shared, 0);   // t -> h (bias+relu)
    k_aggcsr<<<(NN + 7) / 8, 256>>>(nullptr, 1);    // h -> agg
    k_mlp<<<NN / 32, 256>>>(eps_c, eps_n, Wmc, bmc, Wmn, bmn, Wlc, blc, Wln, bln,
                            Wd1c, bd1c, Wd2c, bd2c, Wd1n, bd1n, Wd2n, bd2n,
                            omc, omn, olc, oln);
    k_decode<<<(EE + 255) / 256, 256>>>(oewc, oewn);
}